// round 7
// baseline (speedup 1.0000x reference)
#include <cuda_runtime.h>

// LSTM B=4096, T=999, I=1, H=51, O=1, future=0.
//
// Split-K design: thread = (unit j, gate-pair p, k-half kh).
//   tid = 4*j + 2*p + kh, active tid < 204 (51 units x 4), NTHR=224.
//   p=0 owns gate rows i (j), g (2H+j); p=1 owns f (H+j), o (3H+j) + cell c.
//   kh splits the K=51 dot in half: 13 k-pairs each (26 u64 = 52 weight regs,
//   half of R5 -> 2 CTAs/SM at 224 thr = 14 resident warps vs R5's 8).
// Accumulator slots are (own batches, other batches) so the k-half reduce is
// one-directional: 4 shfl_xor(1) + 4 fadd2, no selects. After the reduce each
// lane post-processes only ITS 2 batches (halves the serial activation tail).
// Gate combine: p0 sends sig(i)*tanh(g) via shfl_xor(2). ONE barrier/step.
// FC output on pad lanes (tid 204..207), deferred one step.

#define HID    51
#define KPH    13         // k-pairs per k-half
#define KP     26
#define SEQLEN 999
#define BT     4
#define NTHR   224
#define BATCH  4096

typedef unsigned long long u64;

__device__ __forceinline__ u64 pk2(float lo, float hi) {
    u64 r;
    asm("mov.b64 %0, {%1, %2};"
        : "=l"(r) : "r"(__float_as_uint(lo)), "r"(__float_as_uint(hi)));
    return r;
}
__device__ __forceinline__ void upk2(u64 v, float& lo, float& hi) {
    unsigned a, b;
    asm("mov.b64 {%0, %1}, %2;" : "=r"(a), "=r"(b) : "l"(v));
    lo = __uint_as_float(a); hi = __uint_as_float(b);
}
__device__ __forceinline__ u64 ffma2(u64 a, u64 b, u64 c) {
    u64 d; asm("fma.rn.f32x2 %0, %1, %2, %3;" : "=l"(d) : "l"(a), "l"(b), "l"(c));
    return d;
}
__device__ __forceinline__ u64 fadd2(u64 a, u64 b) {
    u64 d; asm("add.rn.f32x2 %0, %1, %2;" : "=l"(d) : "l"(a), "l"(b));
    return d;
}
__device__ __forceinline__ float fast_sig_scaled(float a, float kl2) {
    // sigmoid(ks*a), kl2 = -ks*log2(e)
    float e; asm("ex2.approx.f32 %0, %1;" : "=f"(e) : "f"(a * kl2));
    float r; asm("rcp.approx.f32 %0, %1;" : "=f"(r) : "f"(e + 1.0f));
    return r;
}
__device__ __forceinline__ float fast_tanh(float x) {
    float e; asm("ex2.approx.f32 %0, %1;"
                 : "=f"(e) : "f"(x * -2.8853900817779268f));
    float r; asm("rcp.approx.f32 %0, %1;" : "=f"(r) : "f"(e + 1.0f));
    return fmaf(2.0f, r, -1.0f);
}

__global__ __launch_bounds__(NTHR, 2)
void lstm6_kernel(const float* __restrict__ input,   // (B, T, 1)
                  const float* __restrict__ W_ih,    // (4H, 1)
                  const float* __restrict__ W_hh,    // (4H, H)
                  const float* __restrict__ b_ih,    // (4H)
                  const float* __restrict__ b_hh,    // (4H)
                  const float* __restrict__ W_fc,    // (1, H)
                  const float* __restrict__ b_fc,    // (1)
                  float* __restrict__ out)           // (B, T, 1)
{
    __shared__ __align__(16) float xsh[SEQLEN][BT];     // x of 4 batches
    __shared__ __align__(16) u64   hsh[2][KP][BT];      // (h_2k,h_2k+1) x batch
    __shared__ __align__(16) u64   wfc2[KP];

    const int tid = threadIdx.x;
    const int b0  = blockIdx.x * BT;

    // ---- one-time init ----
    #pragma unroll
    for (int b = 0; b < BT; b++)
        for (int idx = tid; idx < SEQLEN; idx += NTHR)
            xsh[idx][b] = input[(b0 + b) * SEQLEN + idx];
    for (int idx = tid; idx < 2 * KP * BT; idx += NTHR)
        ((u64*)hsh)[idx] = 0ull;
    if (tid < KP)
        wfc2[tid] = pk2(W_fc[2 * tid],
                        (2 * tid + 1 < HID) ? W_fc[2 * tid + 1] : 0.0f);

    const int j  = tid >> 2;          // unit 0..50 (active)
    const int p  = (tid >> 1) & 1;    // gate pair: 0=(i,g) 1=(f,o)
    const int kh = tid & 1;           // k-half
    const bool active = (tid < 4 * HID);          // < 204
    const bool fcRole = (tid >= 204 && tid < 208);
    const int  fb     = tid - 204;
    const unsigned wmask = (tid >= 192) ? 0xFFFu : 0xFFFFFFFFu;

    const int row1 = p * HID + j;         // i or f
    const int row2 = (2 + p) * HID + j;   // g or o
    const int kpbase = kh * KPH;

    u64 w1[KPH], w2[KPH];
    float bias1 = 0.f, bias2 = 0.f, wih1 = 0.f, wih2 = 0.f;
    if (active) {
        #pragma unroll
        for (int q = 0; q < KPH; q++) {
            int k0 = 2 * (kpbase + q), k1 = k0 + 1;
            float a0 = W_hh[row1 * HID + k0];
            float a1 = (k1 < HID) ? W_hh[row1 * HID + k1] : 0.0f;
            float c0 = W_hh[row2 * HID + k0];
            float c1 = (k1 < HID) ? W_hh[row2 * HID + k1] : 0.0f;
            w1[q] = pk2(a0, a1);
            w2[q] = pk2(c0, c1);
        }
        bias1 = b_ih[row1] + b_hh[row1];
        bias2 = b_ih[row2] + b_hh[row2];
        wih1  = W_ih[row1];
        wih2  = W_ih[row2];
    } else {
        #pragma unroll
        for (int q = 0; q < KPH; q++) { w1[q] = 0ull; w2[q] = 0ull; }
    }
    const float bfc = b_fc[0];

    // row1 (i|f): sigmoid. row2: tanh for p0 (g), sigmoid for p1 (o).
    const float KL2   = -1.4426950408889634f;
    const float kl2_2 = (p == 0) ? -2.8853900817779268f : -1.4426950408889634f;
    const float mm2   = (p == 0) ? 2.0f : 1.0f;
    const float ba2   = (p == 0) ? -1.0f : 0.0f;

    // batch-slot offsets: "own" = my 2 batches (2*kh), "oth" = partner's
    const int ofOwn = 2 * kh;
    const int ofOth = 2 * (1 - kh);

    u64 c2 = 0ull;    // cell state for my 2 batches (p==1 lanes)

    __syncthreads();

    #pragma unroll 1
    for (int t = 0; t < SEQLEN; t++) {
        const u64* __restrict__ hb = &hsh[t & 1][0][0];

        // ---- deferred FC for step t-1 (pad lanes; stable buffer) ----
        if (fcRole && t > 0) {
            u64 s0 = 0ull, s1 = 0ull;
            #pragma unroll
            for (int q = 0; q < KP; q += 2) {
                s0 = ffma2(hb[q * 4 + fb],       wfc2[q],     s0);
                s1 = ffma2(hb[(q + 1) * 4 + fb], wfc2[q + 1], s1);
            }
            float aa, bb, cc, dd;
            upk2(s0, aa, bb); upk2(s1, cc, dd);
            out[(b0 + fb) * SEQLEN + (t - 1)] = (aa + bb) + (cc + dd) + bfc;
        }

        if (active) {
            // ---- phase 1: half-K dot, 2 rows x (2 own + 2 other) batches ---
            u64 a1o0 = 0ull, a1o1 = 0ull, a1x0 = 0ull, a1x1 = 0ull;
            u64 a2o0 = 0ull, a2o1 = 0ull, a2x0 = 0ull, a2x1 = 0ull;
            const u64* __restrict__ hk = hb + kpbase * 4;
            #pragma unroll
            for (int q = 0; q < KPH; q++) {
                ulonglong2 hOwn = *(const ulonglong2*)(hk + q * 4 + ofOwn);
                ulonglong2 hOth = *(const ulonglong2*)(hk + q * 4 + ofOth);
                a1o0 = ffma2(w1[q], hOwn.x, a1o0);
                a1o1 = ffma2(w1[q], hOwn.y, a1o1);
                a2o0 = ffma2(w2[q], hOwn.x, a2o0);
                a2o1 = ffma2(w2[q], hOwn.y, a2o1);
                a1x0 = ffma2(w1[q], hOth.x, a1x0);
                a1x1 = ffma2(w1[q], hOth.y, a1x1);
                a2x0 = ffma2(w2[q], hOth.x, a2x0);
                a2x1 = ffma2(w2[q], hOth.y, a2x1);
            }

            // ---- k-half reduce: partner's "oth" slots are MY batches ----
            u64 s1b0 = fadd2(a1o0, __shfl_xor_sync(wmask, a1x0, 1, 32));
            u64 s1b1 = fadd2(a1o1, __shfl_xor_sync(wmask, a1x1, 1, 32));
            u64 s2b0 = fadd2(a2o0, __shfl_xor_sync(wmask, a2x0, 1, 32));
            u64 s2b1 = fadd2(a2o1, __shfl_xor_sync(wmask, a2x1, 1, 32));

            // x for my 2 batches (LDS.64 of half the float4 row)
            const float2 xv = ((const float2*)xsh)[t * 2 + kh];

            float lo, hi;
            upk2(s1b0, lo, hi);
            const float g1_0 = (lo + hi) + fmaf(xv.x, wih1, bias1);
            upk2(s1b1, lo, hi);
            const float g1_1 = (lo + hi) + fmaf(xv.y, wih1, bias1);
            upk2(s2b0, lo, hi);
            const float g2_0 = (lo + hi) + fmaf(xv.x, wih2, bias2);
            upk2(s2b1, lo, hi);
            const float g2_1 = (lo + hi) + fmaf(xv.y, wih2, bias2);

            const float act1_0 = fast_sig_scaled(g1_0, KL2);
            const float act1_1 = fast_sig_scaled(g1_1, KL2);
            const float act2_0 = fmaf(mm2, fast_sig_scaled(g2_0, kl2_2), ba2);
            const float act2_1 = fmaf(mm2, fast_sig_scaled(g2_1, kl2_2), ba2);

            // p0 lanes: sig(i)*tanh(g) -> send to p1 partner (xor 2, same kh)
            u64 prod = pk2(act1_0 * act2_0, act1_1 * act2_1);
            u64 r2   = __shfl_xor_sync(wmask, prod, 2, 32);

            if (p == 1) {
                // c = sig(f)*c + sig(i)*tanh(g);  h = sig(o)*tanh(c)
                c2 = ffma2(pk2(act1_0, act1_1), c2, r2);
                float c0, c1;
                upk2(c2, c0, c1);
                const float h0 = act2_0 * fast_tanh(c0);
                const float h1 = act2_1 * fast_tanh(c1);
                // publish: unit j -> pair j>>1, float lane j&1, batches 2kh+.
                float* hn = (float*)&hsh[(t + 1) & 1][j >> 1][ofOwn] + (j & 1);
                hn[0] = h0;
                hn[2] = h1;
            }
        }
        __syncthreads();
    }

    // final FC for t = SEQLEN-1
    if (fcRole) {
        const u64* __restrict__ hv = &hsh[SEQLEN & 1][0][0];
        u64 s0 = 0ull, s1 = 0ull;
        #pragma unroll
        for (int q = 0; q < KP; q += 2) {
            s0 = ffma2(hv[q * 4 + fb],       wfc2[q],     s0);
            s1 = ffma2(hv[(q + 1) * 4 + fb], wfc2[q + 1], s1);
        }
        float aa, bb, cc, dd;
        upk2(s0, aa, bb); upk2(s1, cc, dd);
        out[(b0 + fb) * SEQLEN + (SEQLEN - 1)] = (aa + bb) + (cc + dd) + bfc;
    }
}

extern "C" void kernel_launch(void* const* d_in, const int* in_sizes, int n_in,
                              void* d_out, int out_size) {
    const float* input = (const float*)d_in[0];
    const float* W_ih  = (const float*)d_in[1];
    const float* W_hh  = (const float*)d_in[2];
    const float* b_ih  = (const float*)d_in[3];
    const float* b_hh  = (const float*)d_in[4];
    const float* W_fc  = (const float*)d_in[5];
    const float* b_fc  = (const float*)d_in[6];
    // d_in[7] = future (0) — ignored.
    float* out = (float*)d_out;

    lstm6_kernel<<<BATCH / BT, NTHR>>>(input, W_ih, W_hh, b_ih, b_hh,
                                       W_fc, b_fc, out);
}